// round 9
// baseline (speedup 1.0000x reference)
#include <cuda_runtime.h>

// Problem constants
#define Bb 512
#define Ss 1024
#define Ff 64
#define Ll 128
#define Gg 512   // 4*L
#define BT 4     // batch rows per CTA
#define CR 32    // W cols per gate held in registers
#define CS 96    // W cols per gate streamed from smem (CR + CS = 128)
#define NKG 24   // CS / 4
#define HP 132   // padded h row stride in floats
#define HOFF (4 * HP)

typedef unsigned long long ull;

// ------------------------- device scratch -------------------------
__device__ float g_gx[(size_t)Bb * Ss * Gg];    // x-proj + enc bias, permuted slots (1 GB)
__device__ float g_hall[(size_t)Bb * Ss * Ll];  // decoder h states (256 MB)
__device__ float g_weff[Gg * Ll];               // W_hh_dec + W_ih_dec @ W_dense
__device__ float g_benc[Gg];
__device__ float g_beff[Gg];
__device__ float g_hn[Bb * Ll];
__device__ float g_cn[Bb * Ll];

// ------------------------- helpers -------------------------
__device__ __forceinline__ ull pk(float x, float y) {
    ull r; asm("mov.b64 %0, {%1, %2};" : "=l"(r) : "f"(x), "f"(y)); return r;
}
__device__ __forceinline__ void upk(ull v, float& x, float& y) {
    asm("mov.b64 {%0, %1}, %2;" : "=f"(x), "=f"(y) : "l"(v));
}
__device__ __forceinline__ void fma2(ull& d, ull a, ull b) {
    asm("fma.rn.f32x2 %0, %1, %2, %0;" : "+l"(d) : "l"(a), "l"(b));
}
__device__ __forceinline__ float ex2a(float x) {
    float r; asm("ex2.approx.f32 %0, %1;" : "=f"(r) : "f"(x)); return r;
}
__device__ __forceinline__ float rcpa(float x) {
    float r; asm("rcp.approx.f32 %0, %1;" : "=f"(r) : "f"(x)); return r;
}
__device__ __forceinline__ float fsig(float x) {
    return rcpa(1.0f + ex2a(-1.4426950408889634f * x));
}
__device__ __forceinline__ float ftanh(float x) {
    return fmaf(2.0f, rcpa(1.0f + ex2a(-2.8853900817779268f * x)), -1.0f);
}

// slot offset o -> gate index: order per latent is [i, g, f, o] = gates {0,2,1,3}
__device__ __forceinline__ int gate_of_slot(int s) {
    int o = s & 3;
    int gi = (o == 0) ? 0 : (o == 1) ? 2 : (o == 2) ? 1 : 3;
    return gi * Ll + (s >> 2);
}

// ------------------------- setup: fold decoder matrices -------------------------
__global__ void setup_kernel(const float* __restrict__ Wih_d,
                             const float* __restrict__ Whh_d,
                             const float* __restrict__ bih_d,
                             const float* __restrict__ bhh_d,
                             const float* __restrict__ Wdn,
                             const float* __restrict__ bdn,
                             const float* __restrict__ bih_e,
                             const float* __restrict__ bhh_e) {
    int j = blockIdx.x;   // gate 0..511
    int k = threadIdx.x;  // latent 0..127
    float s = 0.0f;
    for (int m = 0; m < Ff; m++) s += Wih_d[j * Ff + m] * Wdn[m * Ll + k];
    g_weff[j * Ll + k] = Whh_d[j * Ll + k] + s;
    if (k == 0) {
        float bs = bih_d[j] + bhh_d[j];
        for (int m = 0; m < Ff; m++) bs += Wih_d[j * Ff + m] * bdn[m];
        g_beff[j] = bs;
        g_benc[j] = bih_e[j] + bhh_e[j];
    }
}

// ------------------------- x-projection GEMM -------------------------
// Writes gx in permuted slot layout (order [i,g,f,o] per latent).
__global__ void __launch_bounds__(256, 1)
xproj_kernel(const float* __restrict__ x, const float* __restrict__ Wih) {
    extern __shared__ char smraw[];
    ulonglong2* Wsm = (ulonglong2*)smraw;            // [16][512] float4 = 128KB
    float* xs = (float*)(smraw + 16 * 512 * 16);     // [32][64] = 8KB
    const int t_ = threadIdx.x;
    const int sA = t_, sB = t_ + 256;
    const int gA = gate_of_slot(sA);
    const int gB = gate_of_slot(sB);

    const float4* wa = (const float4*)(Wih + gA * Ff);
    const float4* wb = (const float4*)(Wih + gB * Ff);
#pragma unroll
    for (int kg = 0; kg < 16; kg++) {
        ((float4*)Wsm)[kg * 512 + sA] = wa[kg];
        ((float4*)Wsm)[kg * 512 + sB] = wb[kg];
    }
    const float bA = g_benc[gA], bB = g_benc[gB];
    const size_t row0 = (size_t)blockIdx.x * 32;

    ((float4*)xs)[t_]       = ((const float4*)x)[row0 * 16 + t_];
    ((float4*)xs)[t_ + 256] = ((const float4*)x)[row0 * 16 + t_ + 256];
    __syncthreads();

    ull aA[32], aB[32];
#pragma unroll
    for (int r = 0; r < 32; r++) { aA[r] = 0ull; aB[r] = 0ull; }

#pragma unroll 4
    for (int kg = 0; kg < 16; kg++) {
        ulonglong2 wAv = Wsm[kg * 512 + sA];
        ulonglong2 wBv = Wsm[kg * 512 + sB];
#pragma unroll
        for (int r = 0; r < 32; r++) {
            ulonglong2 hh = *(const ulonglong2*)(xs + r * Ff + 4 * kg);
            fma2(aA[r], hh.x, wAv.x); fma2(aA[r], hh.y, wAv.y);
            fma2(aB[r], hh.x, wBv.x); fma2(aB[r], hh.y, wBv.y);
        }
    }
#pragma unroll
    for (int r = 0; r < 32; r++) {
        float lo, hi;
        upk(aA[r], lo, hi); g_gx[(row0 + r) * Gg + sA] = lo + hi + bA;
        upk(aB[r], lo, hi); g_gx[(row0 + r) * Gg + sB] = lo + hi + bB;
    }
}

// ------------------------- recurrent kernels -------------------------
// 512 threads; tid = l*4 + 2*gp + rp.
// Thread owns gates {ga=gp, gb=gp+2} (gp=0 -> {i,g}, gp=1 -> {f,o})
// for batch rows {rp, rp+2}. W: CR cols/gate in regs, CS cols/gate in smem
// laid out [kg][which][gp][l] in float4 units (2 conflict-free wf per load).
// Cell update: gp=0 sends u = sig(i)*tanh(g) via shfl.xor 2; gp=1 owns c, h.
// ONE barrier per step via double-buffered h.

__global__ void __launch_bounds__(512, 1)
enc_kernel(const float* __restrict__ Whh) {
    extern __shared__ char smraw[];
    float4* Wsm = (float4*)smraw;                    // CS*512*4 = 196608 B
    float* hs = (float*)(smraw + CS * Gg * 4);       // [2][4][HP]
    const int tid = threadIdx.x;
    const int l = tid >> 2;
    const int gp = (tid >> 1) & 1;
    const int rp = tid & 1;
    const int b0 = blockIdx.x * BT;
    const int ga = gp, gb = gp + 2;

    ull WrA[CR / 2], WrB[CR / 2];
    {
        const float4* wa = (const float4*)(Whh + (ga * Ll + l) * Ll);
        const float4* wb = (const float4*)(Whh + (gb * Ll + l) * Ll);
#pragma unroll
        for (int q = 0; q < CR / 4; q++) {
            float4 v = wa[q]; WrA[2 * q] = pk(v.x, v.y); WrA[2 * q + 1] = pk(v.z, v.w);
            float4 u = wb[q]; WrB[2 * q] = pk(u.x, u.y); WrB[2 * q + 1] = pk(u.z, u.w);
        }
        const float* wrow = Whh + ((rp == 0 ? ga : gb) * Ll + l) * Ll;
#pragma unroll
        for (int kg = 0; kg < NKG; kg++)
            Wsm[((kg * 2 + rp) * 2 + gp) * 128 + l] = *(const float4*)(wrow + CR + 4 * kg);
    }
    if (gp == 0) {
        hs[rp * HP + l] = 0.0f;
        hs[(rp + 2) * HP + l] = 0.0f;
    }
    float c0 = 0.0f, c1 = 0.0f;
    __syncthreads();

    for (int t = 0; t < Ss; t++) {
        float2 gx0 = *(const float2*)(g_gx + ((size_t)(b0 + rp) * Ss + t) * Gg + l * 4 + 2 * gp);
        float2 gx1 = *(const float2*)(g_gx + ((size_t)(b0 + rp + 2) * Ss + t) * Gg + l * 4 + 2 * gp);
        const float* h0p = hs + (t & 1) * HOFF + rp * HP;
        const float* h1p = hs + (t & 1) * HOFF + (rp + 2) * HP;
        ull aA0 = 0, aB0 = 0, aA1 = 0, aB1 = 0;
#pragma unroll
        for (int q = 0; q < CR / 4; q++) {
            ulonglong2 h0 = *(const ulonglong2*)(h0p + 4 * q);
            ulonglong2 h1 = *(const ulonglong2*)(h1p + 4 * q);
            fma2(aA0, h0.x, WrA[2 * q]); fma2(aA0, h0.y, WrA[2 * q + 1]);
            fma2(aB0, h0.x, WrB[2 * q]); fma2(aB0, h0.y, WrB[2 * q + 1]);
            fma2(aA1, h1.x, WrA[2 * q]); fma2(aA1, h1.y, WrA[2 * q + 1]);
            fma2(aB1, h1.x, WrB[2 * q]); fma2(aB1, h1.y, WrB[2 * q + 1]);
        }
#pragma unroll
        for (int kg = 0; kg < NKG; kg++) {
            ulonglong2 wA = *(const ulonglong2*)&Wsm[((kg * 2 + 0) * 2 + gp) * 128 + l];
            ulonglong2 wB = *(const ulonglong2*)&Wsm[((kg * 2 + 1) * 2 + gp) * 128 + l];
            ulonglong2 h0 = *(const ulonglong2*)(h0p + CR + 4 * kg);
            ulonglong2 h1 = *(const ulonglong2*)(h1p + CR + 4 * kg);
            fma2(aA0, h0.x, wA.x); fma2(aA0, h0.y, wA.y);
            fma2(aB0, h0.x, wB.x); fma2(aB0, h0.y, wB.y);
            fma2(aA1, h1.x, wA.x); fma2(aA1, h1.y, wA.y);
            fma2(aB1, h1.x, wB.x); fma2(aB1, h1.y, wB.y);
        }
        float lo, hi;
        upk(aA0, lo, hi); float va0 = lo + hi + gx0.x;
        upk(aB0, lo, hi); float vb0 = lo + hi + gx0.y;
        upk(aA1, lo, hi); float va1 = lo + hi + gx1.x;
        upk(aB1, lo, hi); float vb1 = lo + hi + gx1.y;
        // gp=0: va=i, vb=g -> u = sig(i)*tanh(g). gp=1 computes junk (unused).
        float u0 = fsig(va0) * ftanh(vb0);
        float u1 = fsig(va1) * ftanh(vb1);
        float p0 = __shfl_xor_sync(0xffffffffu, u0, 2);
        float p1 = __shfl_xor_sync(0xffffffffu, u1, 2);
        if (gp) {   // va=f, vb=o
            float* hn = hs + ((t + 1) & 1) * HOFF;
            c0 = fsig(va0) * c0 + p0;
            c1 = fsig(va1) * c1 + p1;
            hn[rp * HP + l] = fsig(vb0) * ftanh(c0);
            hn[(rp + 2) * HP + l] = fsig(vb1) * ftanh(c1);
        }
        __syncthreads();
    }
    if (gp) {
        const float* hf = hs + (Ss & 1) * HOFF;
        g_hn[(b0 + rp) * Ll + l] = hf[rp * HP + l];
        g_hn[(b0 + rp + 2) * Ll + l] = hf[(rp + 2) * HP + l];
        g_cn[(b0 + rp) * Ll + l] = c0;
        g_cn[(b0 + rp + 2) * Ll + l] = c1;
    }
}

__global__ void __launch_bounds__(512, 1)
dec_kernel() {
    extern __shared__ char smraw[];
    float4* Wsm = (float4*)smraw;
    float* hs = (float*)(smraw + CS * Gg * 4);
    const int tid = threadIdx.x;
    const int l = tid >> 2;
    const int gp = (tid >> 1) & 1;
    const int rp = tid & 1;
    const int b0 = blockIdx.x * BT;
    const int ga = gp, gb = gp + 2;

    ull WrA[CR / 2], WrB[CR / 2];
    {
        const float4* wa = (const float4*)(g_weff + (ga * Ll + l) * Ll);
        const float4* wb = (const float4*)(g_weff + (gb * Ll + l) * Ll);
#pragma unroll
        for (int q = 0; q < CR / 4; q++) {
            float4 v = wa[q]; WrA[2 * q] = pk(v.x, v.y); WrA[2 * q + 1] = pk(v.z, v.w);
            float4 u = wb[q]; WrB[2 * q] = pk(u.x, u.y); WrB[2 * q + 1] = pk(u.z, u.w);
        }
        const float* wrow = g_weff + ((rp == 0 ? ga : gb) * Ll + l) * Ll;
#pragma unroll
        for (int kg = 0; kg < NKG; kg++)
            Wsm[((kg * 2 + rp) * 2 + gp) * 128 + l] = *(const float4*)(wrow + CR + 4 * kg);
    }
    const float beA = g_beff[ga * Ll + l];
    const float beB = g_beff[gb * Ll + l];
    if (gp == 0) {
        hs[rp * HP + l] = g_hn[(b0 + rp) * Ll + l];
        hs[(rp + 2) * HP + l] = g_hn[(b0 + rp + 2) * Ll + l];
    }
    float c0 = g_cn[(b0 + rp) * Ll + l];
    float c1 = g_cn[(b0 + rp + 2) * Ll + l];
    float* ho0 = g_hall + ((size_t)(b0 + rp) * Ss) * Ll + l;
    float* ho1 = g_hall + ((size_t)(b0 + rp + 2) * Ss) * Ll + l;
    __syncthreads();

    for (int t = 0; t < Ss; t++) {
        const float* h0p = hs + (t & 1) * HOFF + rp * HP;
        const float* h1p = hs + (t & 1) * HOFF + (rp + 2) * HP;
        ull aA0 = 0, aB0 = 0, aA1 = 0, aB1 = 0;
#pragma unroll
        for (int q = 0; q < CR / 4; q++) {
            ulonglong2 h0 = *(const ulonglong2*)(h0p + 4 * q);
            ulonglong2 h1 = *(const ulonglong2*)(h1p + 4 * q);
            fma2(aA0, h0.x, WrA[2 * q]); fma2(aA0, h0.y, WrA[2 * q + 1]);
            fma2(aB0, h0.x, WrB[2 * q]); fma2(aB0, h0.y, WrB[2 * q + 1]);
            fma2(aA1, h1.x, WrA[2 * q]); fma2(aA1, h1.y, WrA[2 * q + 1]);
            fma2(aB1, h1.x, WrB[2 * q]); fma2(aB1, h1.y, WrB[2 * q + 1]);
        }
#pragma unroll
        for (int kg = 0; kg < NKG; kg++) {
            ulonglong2 wA = *(const ulonglong2*)&Wsm[((kg * 2 + 0) * 2 + gp) * 128 + l];
            ulonglong2 wB = *(const ulonglong2*)&Wsm[((kg * 2 + 1) * 2 + gp) * 128 + l];
            ulonglong2 h0 = *(const ulonglong2*)(h0p + CR + 4 * kg);
            ulonglong2 h1 = *(const ulonglong2*)(h1p + CR + 4 * kg);
            fma2(aA0, h0.x, wA.x); fma2(aA0, h0.y, wA.y);
            fma2(aB0, h0.x, wB.x); fma2(aB0, h0.y, wB.y);
            fma2(aA1, h1.x, wA.x); fma2(aA1, h1.y, wA.y);
            fma2(aB1, h1.x, wB.x); fma2(aB1, h1.y, wB.y);
        }
        float lo, hi;
        upk(aA0, lo, hi); float va0 = lo + hi + beA;
        upk(aB0, lo, hi); float vb0 = lo + hi + beB;
        upk(aA1, lo, hi); float va1 = lo + hi + beA;
        upk(aB1, lo, hi); float vb1 = lo + hi + beB;
        float u0 = fsig(va0) * ftanh(vb0);
        float u1 = fsig(va1) * ftanh(vb1);
        float p0 = __shfl_xor_sync(0xffffffffu, u0, 2);
        float p1 = __shfl_xor_sync(0xffffffffu, u1, 2);
        if (gp) {
            float* hn = hs + ((t + 1) & 1) * HOFF;
            c0 = fsig(va0) * c0 + p0;
            c1 = fsig(va1) * c1 + p1;
            float h0n = fsig(vb0) * ftanh(c0);
            float h1n = fsig(vb1) * ftanh(c1);
            hn[rp * HP + l] = h0n;
            hn[(rp + 2) * HP + l] = h1n;
            ho0[(size_t)t * Ll] = h0n;   // g_hall[b][t][l] = H_{t+1}
            ho1[(size_t)t * Ll] = h1n;
        }
        __syncthreads();
    }
}

// ------------------------- output GEMM + flip -------------------------
__global__ void __launch_bounds__(256, 1)
out_kernel(const float* __restrict__ Wdn, const float* __restrict__ bdn,
           float* __restrict__ out) {
    extern __shared__ float hsm[];   // [128][128] = 64KB
    const int tid = threadIdx.x;
    const size_t row0 = (size_t)blockIdx.x * 128;
    for (int i = tid; i < 128 * Ll / 4; i += 256)
        ((float4*)hsm)[i] = ((const float4*)g_hall)[row0 * (Ll / 4) + i];

    const int f = tid & 63, rg = tid >> 6;
    ull Wd[64];
    const float4* wd = (const float4*)(Wdn + f * Ll);
#pragma unroll
    for (int q = 0; q < 32; q++) {
        float4 v = wd[q];
        Wd[2 * q] = pk(v.x, v.y); Wd[2 * q + 1] = pk(v.z, v.w);
    }
    const float bv = bdn[f];
    __syncthreads();

#pragma unroll 1
    for (int rr = 0; rr < 32; rr += 2) {
        int row = rg * 32 + rr;
        ull a0 = 0, a1 = 0;
#pragma unroll
        for (int q = 0; q < 32; q++) {
            ulonglong2 h0 = *(const ulonglong2*)(hsm + row * Ll + 4 * q);
            ulonglong2 h1 = *(const ulonglong2*)(hsm + (row + 1) * Ll + 4 * q);
            fma2(a0, h0.x, Wd[2 * q]); fma2(a0, h0.y, Wd[2 * q + 1]);
            fma2(a1, h1.x, Wd[2 * q]); fma2(a1, h1.y, Wd[2 * q + 1]);
        }
        float lo, hi;
        upk(a0, lo, hi); float s0 = lo + hi + bv;
        upk(a1, lo, hi); float s1 = lo + hi + bv;
        size_t g0 = row0 + row;
        size_t b_ = g0 >> 10; int t_ = (int)(g0 & 1023);
        out[(b_ * Ss + (size_t)(Ss - 1 - t_)) * Ff + f] = s0;
        g0 += 1;
        b_ = g0 >> 10; t_ = (int)(g0 & 1023);
        out[(b_ * Ss + (size_t)(Ss - 1 - t_)) * Ff + f] = s1;
    }
}

// ------------------------- launch -------------------------
extern "C" void kernel_launch(void* const* d_in, const int* in_sizes, int n_in,
                              void* d_out, int out_size) {
    const float* x     = (const float*)d_in[0];
    const float* Wih_e = (const float*)d_in[1];
    const float* Whh_e = (const float*)d_in[2];
    const float* bih_e = (const float*)d_in[3];
    const float* bhh_e = (const float*)d_in[4];
    const float* Wih_d = (const float*)d_in[5];
    const float* Whh_d = (const float*)d_in[6];
    const float* bih_d = (const float*)d_in[7];
    const float* bhh_d = (const float*)d_in[8];
    const float* Wdn   = (const float*)d_in[9];
    const float* bdn   = (const float*)d_in[10];
    float* out = (float*)d_out;

    const int SM_X = 16 * 512 * 16 + 32 * 64 * 4;     // 139264
    const int SM_R = CS * Gg * 4 + 2 * HOFF * 4;      // 196608 + 4224 = 200832
    const int SM_O = 128 * Ll * 4;                    // 65536

    cudaFuncSetAttribute(xproj_kernel, cudaFuncAttributeMaxDynamicSharedMemorySize, SM_X);
    cudaFuncSetAttribute(enc_kernel,   cudaFuncAttributeMaxDynamicSharedMemorySize, SM_R);
    cudaFuncSetAttribute(dec_kernel,   cudaFuncAttributeMaxDynamicSharedMemorySize, SM_R);
    cudaFuncSetAttribute(out_kernel,   cudaFuncAttributeMaxDynamicSharedMemorySize, SM_O);

    setup_kernel<<<Gg, Ll>>>(Wih_d, Whh_d, bih_d, bhh_d, Wdn, bdn, bih_e, bhh_e);
    xproj_kernel<<<(Bb * Ss) / 32, 256, SM_X>>>(x, Wih_e);
    enc_kernel<<<Bb / BT, 512, SM_R>>>(Whh_e);
    dec_kernel<<<Bb / BT, 512, SM_R>>>();
    out_kernel<<<(Bb * Ss) / 128, 256, SM_O>>>(Wdn, bdn, out);
}